// round 1
// baseline (speedup 1.0000x reference)
#include <cuda_runtime.h>

// ---------------------------------------------------------------------------
// FeatureFusionModule: B=8, C=512, H=W=64, N=4096, heads=8, d=64
// Layouts: activations kept as (B, N, C) row-major (C contiguous).
// ---------------------------------------------------------------------------

#define Bb 8
#define Cc 512
#define Nn 4096
#define Mtot (Bb * Nn)   // 32768

// ------------------------------- scratch -----------------------------------
__device__ float g_r   [(size_t)Bb * Nn * Cc];        // rgb transposed (B,N,C)
__device__ float g_x   [(size_t)Bb * Nn * Cc];        // x transposed
__device__ float g_yr  [(size_t)Bb * Nn * 2 * Cc];    // [y_rgb | o_rgb]
__device__ float g_yx  [(size_t)Bb * Nn * 2 * Cc];    // [y_x | o_x]
__device__ float g_ur  [(size_t)Bb * Nn * Cc];        // u_rgb
__device__ float g_ux  [(size_t)Bb * Nn * Cc];        // u_x
__device__ float g_kvr [(size_t)Bb * Nn * 2 * Cc];
__device__ float g_kvx [(size_t)Bb * Nn * 2 * Cc];
__device__ float g_ctx [2 * 64 * 64 * 64];            // [tensor][bh][d][e]
__device__ float g_attp[2 * 64 * 16 * 64 * 64];       // kTv partials, 16-way n split
__device__ float g_fuse[(size_t)Bb * Nn * 2 * Cc];    // [out_r | out_x]
__device__ float g_res [(size_t)Bb * Nn * Cc];
__device__ float g_t1  [(size_t)Bb * Nn * Cc];
__device__ float g_t2  [(size_t)Bb * Nn * Cc];
__device__ float g_bnp [2 * 256 * Cc];                // BN partial sums / sumsq
__device__ float g_mu  [Cc];
__device__ float g_rs  [Cc];

// ------------------------- transpose NCHW -> (B,N,C) ------------------------
__global__ void transpose_cn_to_nc(const float* __restrict__ in, float* __restrict__ out) {
    __shared__ float tile[32][33];
    int b = blockIdx.z;
    int n0 = blockIdx.x * 32, c0 = blockIdx.y * 32;
    const float* ip = in + (size_t)b * Cc * Nn;
    float* op = out + (size_t)b * Nn * Cc;
    int tx = threadIdx.x, ty = threadIdx.y;
    #pragma unroll
    for (int i = ty; i < 32; i += 8)
        tile[i][tx] = ip[(size_t)(c0 + i) * Nn + n0 + tx];
    __syncthreads();
    #pragma unroll
    for (int i = ty; i < 32; i += 8)
        op[(size_t)(n0 + i) * Cc + c0 + tx] = tile[tx][i];
}

// ------------------------------ generic SGEMM -------------------------------
// C[m,n] = act( sum_k A[m,k] * Bw[n,k] + bias[n] + resid[m,n] )
// M = gridDim.y*128, N = gridDim.x*128. All dims divisible: no guards.
__global__ __launch_bounds__(256) void sgemm_nt(
    const float* __restrict__ A, int lda,
    const float* __restrict__ Bw, int ldb,
    const float* __restrict__ bias,
    const float* __restrict__ resid, int ldr,
    float* __restrict__ C, int ldc,
    int K, int relu)
{
    __shared__ float As[16][132];
    __shared__ float Bs[16][132];
    const int tid = threadIdx.x;
    const int bm = blockIdx.y * 128;
    const int bn = blockIdx.x * 128;
    const int tr = tid >> 4;        // 0..15
    const int tc = tid & 15;        // 0..15
    const int arow = tid >> 2;      // 0..63
    const int acol = (tid & 3) << 2; // 0,4,8,12

    float acc[8][8];
    #pragma unroll
    for (int i = 0; i < 8; i++)
        #pragma unroll
        for (int j = 0; j < 8; j++) acc[i][j] = 0.f;

    for (int k0 = 0; k0 < K; k0 += 16) {
        #pragma unroll
        for (int h = 0; h < 2; h++) {
            int r = arow + 64 * h;
            float4 va = *(const float4*)(A  + (size_t)(bm + r) * lda + k0 + acol);
            As[acol + 0][r] = va.x; As[acol + 1][r] = va.y;
            As[acol + 2][r] = va.z; As[acol + 3][r] = va.w;
            float4 vb = *(const float4*)(Bw + (size_t)(bn + r) * ldb + k0 + acol);
            Bs[acol + 0][r] = vb.x; Bs[acol + 1][r] = vb.y;
            Bs[acol + 2][r] = vb.z; Bs[acol + 3][r] = vb.w;
        }
        __syncthreads();
        #pragma unroll
        for (int k = 0; k < 16; k++) {
            float a[8], b[8];
            float4 a0 = *(float4*)&As[k][tr * 8];
            float4 a1 = *(float4*)&As[k][tr * 8 + 4];
            a[0]=a0.x; a[1]=a0.y; a[2]=a0.z; a[3]=a0.w;
            a[4]=a1.x; a[5]=a1.y; a[6]=a1.z; a[7]=a1.w;
            float4 b0 = *(float4*)&Bs[k][tc * 8];
            float4 b1 = *(float4*)&Bs[k][tc * 8 + 4];
            b[0]=b0.x; b[1]=b0.y; b[2]=b0.z; b[3]=b0.w;
            b[4]=b1.x; b[5]=b1.y; b[6]=b1.z; b[7]=b1.w;
            #pragma unroll
            for (int i = 0; i < 8; i++)
                #pragma unroll
                for (int j = 0; j < 8; j++)
                    acc[i][j] += a[i] * b[j];
        }
        __syncthreads();
    }

    #pragma unroll
    for (int i = 0; i < 8; i++) {
        int m = bm + tr * 8 + i;
        #pragma unroll
        for (int j = 0; j < 8; j++) {
            int n = bn + tc * 8 + j;
            float v = acc[i][j];
            if (bias)  v += bias[n];
            if (resid) v += resid[(size_t)m * ldr + n];
            if (relu)  v = fmaxf(v, 0.f);
            C[(size_t)m * ldc + n] = v;
        }
    }
}

// --------------------------- attention: kT v partials -----------------------
// grid = (64 bh, 16 split), block 256. part[(bh*16+s)*4096 + d*64 + e]
__global__ __launch_bounds__(256) void attn_ktv(const float* __restrict__ kv,
                                                float* __restrict__ part) {
    __shared__ float ks[32][68];
    __shared__ float vs[32][68];
    int bh = blockIdx.x;
    int b = bh >> 3, h = bh & 7;
    int s = blockIdx.y;
    const float* kp = kv + (size_t)b * Nn * 1024 + h * 64;
    const float* vp = kp + 512;
    int tid = threadIdx.x;
    int td = tid >> 4, te = tid & 15;
    float acc[4][4];
    #pragma unroll
    for (int i = 0; i < 4; i++)
        #pragma unroll
        for (int j = 0; j < 4; j++) acc[i][j] = 0.f;

    for (int n0 = s * 256; n0 < s * 256 + 256; n0 += 32) {
        #pragma unroll
        for (int hh = 0; hh < 2; hh++) {
            int flat = tid + 256 * hh;
            int row = flat >> 4;
            int cv = (flat & 15) << 2;
            *(float4*)&ks[row][cv] = *(const float4*)(kp + (size_t)(n0 + row) * 1024 + cv);
            *(float4*)&vs[row][cv] = *(const float4*)(vp + (size_t)(n0 + row) * 1024 + cv);
        }
        __syncthreads();
        #pragma unroll
        for (int nn = 0; nn < 32; nn++) {
            float av[4], bv[4];
            float4 a4 = *(float4*)&ks[nn][td * 4];
            av[0]=a4.x; av[1]=a4.y; av[2]=a4.z; av[3]=a4.w;
            float4 b4 = *(float4*)&vs[nn][te * 4];
            bv[0]=b4.x; bv[1]=b4.y; bv[2]=b4.z; bv[3]=b4.w;
            #pragma unroll
            for (int i = 0; i < 4; i++)
                #pragma unroll
                for (int j = 0; j < 4; j++)
                    acc[i][j] += av[i] * bv[j];
        }
        __syncthreads();
    }
    float* pp = part + ((size_t)bh * 16 + s) * 4096;
    #pragma unroll
    for (int i = 0; i < 4; i++)
        #pragma unroll
        for (int j = 0; j < 4; j++)
            pp[(td * 4 + i) * 64 + te * 4 + j] = acc[i][j];
}

// ------------------- reduce partials, scale, softmax over d -----------------
// grid = 64 (bh), block 64 (thread = e)
__global__ void attn_reduce_softmax(const float* __restrict__ part,
                                    float* __restrict__ ctx) {
    int bh = blockIdx.x;
    int e = threadIdx.x;
    float m[64];
    #pragma unroll
    for (int d = 0; d < 64; d++) {
        float ssum = 0.f;
        #pragma unroll
        for (int p = 0; p < 16; p++)
            ssum += part[((size_t)bh * 16 + p) * 4096 + d * 64 + e];
        m[d] = ssum * 0.125f;   // scale = 64^-0.5
    }
    float mx = -1e30f;
    #pragma unroll
    for (int d = 0; d < 64; d++) mx = fmaxf(mx, m[d]);
    float sum = 0.f;
    #pragma unroll
    for (int d = 0; d < 64; d++) { m[d] = expf(m[d] - mx); sum += m[d]; }
    float inv = 1.f / sum;
    #pragma unroll
    for (int d = 0; d < 64; d++)
        ctx[(size_t)bh * 4096 + d * 64 + e] = m[d] * inv;
}

// ------------------------------- o = q @ ctx --------------------------------
// grid = (64 n-chunks of 64, 64 bh), block 256. outp pre-offset by +512 col.
__global__ __launch_bounds__(256) void attn_qctx(const float* __restrict__ q,
                                                 const float* __restrict__ ctx,
                                                 float* __restrict__ outp) {
    __shared__ float cs[64][68];
    __shared__ float qs[64][68];
    int bh = blockIdx.y;
    int b = bh >> 3, h = bh & 7;
    const float* cp = ctx + (size_t)bh * 4096;
    int tid = threadIdx.x;
    for (int i = tid; i < 4096; i += 256)
        cs[i >> 6][i & 63] = cp[i];
    int n0 = blockIdx.x * 64;
    const float* qp = q + (size_t)b * Nn * Cc + h * 64;
    #pragma unroll
    for (int j = 0; j < 4; j++) {
        int flat = tid + 256 * j;
        int row = flat >> 4;
        int cv = (flat & 15) << 2;
        *(float4*)&qs[row][cv] = *(const float4*)(qp + (size_t)(n0 + row) * Cc + cv);
    }
    __syncthreads();
    int tn = tid >> 3;  // 0..31
    int te = tid & 7;   // 0..7
    float acc0[8], acc1[8];
    #pragma unroll
    for (int j = 0; j < 8; j++) { acc0[j] = 0.f; acc1[j] = 0.f; }
    #pragma unroll 4
    for (int d = 0; d < 64; d++) {
        float qa = qs[tn][d];
        float qb = qs[tn + 32][d];
        float4 c0 = *(float4*)&cs[d][te * 8];
        float4 c1 = *(float4*)&cs[d][te * 8 + 4];
        float cv[8];
        cv[0]=c0.x; cv[1]=c0.y; cv[2]=c0.z; cv[3]=c0.w;
        cv[4]=c1.x; cv[5]=c1.y; cv[6]=c1.z; cv[7]=c1.w;
        #pragma unroll
        for (int j = 0; j < 8; j++) {
            acc0[j] += qa * cv[j];
            acc1[j] += qb * cv[j];
        }
    }
    float* o0 = outp + ((size_t)b * Nn + n0 + tn) * 1024 + h * 64 + te * 8;
    float* o1 = outp + ((size_t)b * Nn + n0 + tn + 32) * 1024 + h * 64 + te * 8;
    #pragma unroll
    for (int j = 0; j < 8; j++) { o0[j] = acc0[j]; o1[j] = acc1[j]; }
}

// ------------------------------ layernorm rows ------------------------------
// one block (128 thr) per row of width 512, in place
__global__ __launch_bounds__(128) void layernorm_rows(float* __restrict__ base, int ld,
                                                      const float* __restrict__ gg,
                                                      const float* __restrict__ bb) {
    int row = blockIdx.x;
    float* p = base + (size_t)row * ld;
    int t = threadIdx.x;
    float v[4];
    float s = 0.f;
    #pragma unroll
    for (int i = 0; i < 4; i++) { v[i] = p[t + i * 128]; s += v[i]; }
    __shared__ float red[4];
    #pragma unroll
    for (int o = 16; o > 0; o >>= 1) s += __shfl_xor_sync(0xffffffffu, s, o);
    if ((t & 31) == 0) red[t >> 5] = s;
    __syncthreads();
    float mu = (red[0] + red[1] + red[2] + red[3]) * (1.f / 512.f);
    float q = 0.f;
    #pragma unroll
    for (int i = 0; i < 4; i++) { float d = v[i] - mu; q += d * d; }
    #pragma unroll
    for (int o = 16; o > 0; o >>= 1) q += __shfl_xor_sync(0xffffffffu, q, o);
    __syncthreads();
    if ((t & 31) == 0) red[t >> 5] = q;
    __syncthreads();
    float rs = rsqrtf((red[0] + red[1] + red[2] + red[3]) * (1.f / 512.f) + 1e-5f);
    #pragma unroll
    for (int i = 0; i < 4; i++) {
        int c = t + i * 128;
        p[c] = (v[i] - mu) * rs * gg[c] + bb[c];
    }
}

// --------------------------- depthwise 3x3 + relu ---------------------------
__global__ void dwconv3x3(const float* __restrict__ in, const float* __restrict__ w,
                          const float* __restrict__ bias, float* __restrict__ out) {
    int idx = blockIdx.x * 256 + threadIdx.x;  // B*N*C = 16,777,216
    int c = idx & 511;
    int n = (idx >> 9) & 4095;
    int b = idx >> 21;
    int h = n >> 6, ww = n & 63;
    float acc = bias[c];
    #pragma unroll
    for (int kh = 0; kh < 3; kh++) {
        int hh = h + kh - 1;
        if ((unsigned)hh >= 64u) continue;
        #pragma unroll
        for (int kw = 0; kw < 3; kw++) {
            int wc = ww + kw - 1;
            if ((unsigned)wc >= 64u) continue;
            acc += in[((size_t)b * Nn + hh * 64 + wc) * Cc + c] * w[c * 9 + kh * 3 + kw];
        }
    }
    out[idx] = fmaxf(acc, 0.f);
}

// ------------------------------- batchnorm ----------------------------------
// partial: 256 blocks x 128 rows each, per-channel sum & sumsq
__global__ __launch_bounds__(256) void bn_stats_partial(const float* __restrict__ X,
                                                        float* __restrict__ part) {
    int blk = blockIdx.x;
    const float* p = X + (size_t)blk * 128 * Cc;
    int c0 = threadIdx.x, c1 = threadIdx.x + 256;
    float s0 = 0.f, q0 = 0.f, s1 = 0.f, q1 = 0.f;
    for (int r = 0; r < 128; r++) {
        float a = p[(size_t)r * Cc + c0];
        s0 += a; q0 += a * a;
        float bv = p[(size_t)r * Cc + c1];
        s1 += bv; q1 += bv * bv;
    }
    part[(size_t)blk * Cc + c0] = s0;
    part[(size_t)blk * Cc + c1] = s1;
    part[(size_t)256 * Cc + blk * Cc + c0] = q0;
    part[(size_t)256 * Cc + blk * Cc + c1] = q1;
}

__global__ void bn_stats_final(const float* __restrict__ part,
                               float* __restrict__ mu, float* __restrict__ rs) {
    int c = threadIdx.x;  // 512 threads, 1 block
    float s = 0.f, q = 0.f;
    for (int p = 0; p < 256; p++) {
        s += part[(size_t)p * Cc + c];
        q += part[(size_t)256 * Cc + p * Cc + c];
    }
    float m = s * (1.f / 32768.f);
    float v = q * (1.f / 32768.f) - m * m;
    mu[c] = m;
    rs[c] = rsqrtf(v + 1e-5f);
}

// s = resid + bn1(t3)
__global__ void bn_apply_add(const float* __restrict__ t3, const float* __restrict__ res,
                             const float* __restrict__ mu, const float* __restrict__ rs,
                             const float* __restrict__ gg, const float* __restrict__ bb,
                             float* __restrict__ s) {
    int idx = blockIdx.x * 256 + threadIdx.x;
    int c = idx & 511;
    s[idx] = res[idx] + (t3[idx] - mu[c]) * rs[c] * gg[c] + bb[c];
}

// final: bn2 + transpose (B,N,C) -> NCHW
__global__ void bn_apply_transpose(const float* __restrict__ s,
                                   const float* __restrict__ mu, const float* __restrict__ rs,
                                   const float* __restrict__ gg, const float* __restrict__ bb,
                                   float* __restrict__ out) {
    __shared__ float tile[32][33];
    int b = blockIdx.z;
    int n0 = blockIdx.x * 32, c0 = blockIdx.y * 32;
    const float* ps = s + (size_t)b * Nn * Cc;
    float* po = out + (size_t)b * Cc * Nn;
    int tx = threadIdx.x, ty = threadIdx.y;
    #pragma unroll
    for (int i = ty; i < 32; i += 8) {
        int c = c0 + tx;
        float v = ps[(size_t)(n0 + i) * Cc + c];
        tile[i][tx] = (v - mu[c]) * rs[c] * gg[c] + bb[c];
    }
    __syncthreads();
    #pragma unroll
    for (int i = ty; i < 32; i += 8)
        po[(size_t)(c0 + i) * Nn + n0 + tx] = tile[tx][i];
}

// --------------------------------- launch -----------------------------------
extern "C" void kernel_launch(void* const* d_in, const int* in_sizes, int n_in,
                              void* d_out, int out_size) {
    (void)in_sizes; (void)n_in; (void)out_size;
    const float* rgb        = (const float*)d_in[0];
    const float* x          = (const float*)d_in[1];
    const float* W_rgb_proj = (const float*)d_in[2];
    const float* b_rgb_proj = (const float*)d_in[3];
    const float* W_x_proj   = (const float*)d_in[4];
    const float* b_x_proj   = (const float*)d_in[5];
    const float* W_kv_rgb   = (const float*)d_in[6];
    const float* W_kv_x     = (const float*)d_in[7];
    const float* W_out_rgb  = (const float*)d_in[8];
    const float* b_out_rgb  = (const float*)d_in[9];
    const float* W_out_x    = (const float*)d_in[10];
    const float* b_out_x    = (const float*)d_in[11];
    const float* ln_rgb_g   = (const float*)d_in[12];
    const float* ln_rgb_b   = (const float*)d_in[13];
    const float* ln_x_g     = (const float*)d_in[14];
    const float* ln_x_b     = (const float*)d_in[15];
    const float* W_res      = (const float*)d_in[16];
    const float* W_ce1      = (const float*)d_in[17];
    const float* b_ce1      = (const float*)d_in[18];
    const float* W_dw       = (const float*)d_in[19];
    const float* b_dw       = (const float*)d_in[20];
    const float* W_ce2      = (const float*)d_in[21];
    const float* b_ce2      = (const float*)d_in[22];
    const float* bn1_g      = (const float*)d_in[23];
    const float* bn1_b      = (const float*)d_in[24];
    const float* bn2_g      = (const float*)d_in[25];
    const float* bn2_b      = (const float*)d_in[26];
    float* out = (float*)d_out;

    float *p_r, *p_x, *p_yr, *p_yx, *p_ur, *p_ux, *p_kvr, *p_kvx;
    float *p_ctx, *p_attp, *p_fuse, *p_res, *p_t1, *p_t2, *p_bnp, *p_mu, *p_rs;
    cudaGetSymbolAddress((void**)&p_r,    g_r);
    cudaGetSymbolAddress((void**)&p_x,    g_x);
    cudaGetSymbolAddress((void**)&p_yr,   g_yr);
    cudaGetSymbolAddress((void**)&p_yx,   g_yx);
    cudaGetSymbolAddress((void**)&p_ur,   g_ur);
    cudaGetSymbolAddress((void**)&p_ux,   g_ux);
    cudaGetSymbolAddress((void**)&p_kvr,  g_kvr);
    cudaGetSymbolAddress((void**)&p_kvx,  g_kvx);
    cudaGetSymbolAddress((void**)&p_ctx,  g_ctx);
    cudaGetSymbolAddress((void**)&p_attp, g_attp);
    cudaGetSymbolAddress((void**)&p_fuse, g_fuse);
    cudaGetSymbolAddress((void**)&p_res,  g_res);
    cudaGetSymbolAddress((void**)&p_t1,   g_t1);
    cudaGetSymbolAddress((void**)&p_t2,   g_t2);
    cudaGetSymbolAddress((void**)&p_bnp,  g_bnp);
    cudaGetSymbolAddress((void**)&p_mu,   g_mu);
    cudaGetSymbolAddress((void**)&p_rs,   g_rs);

    dim3 tp_grid(128, 16, 8), tp_blk(32, 8);

    // 1. transposes
    transpose_cn_to_nc<<<tp_grid, tp_blk>>>(rgb, p_r);
    transpose_cn_to_nc<<<tp_grid, tp_blk>>>(x,   p_x);

    // 2. projections (split y / u, relu)
    sgemm_nt<<<dim3(4, 256), 256>>>(p_r, 512, W_rgb_proj,            512, b_rgb_proj,       nullptr, 0, p_yr, 1024, 512, 1);
    sgemm_nt<<<dim3(4, 256), 256>>>(p_r, 512, W_rgb_proj + 512*512,  512, b_rgb_proj + 512, nullptr, 0, p_ur, 512,  512, 1);
    sgemm_nt<<<dim3(4, 256), 256>>>(p_x, 512, W_x_proj,              512, b_x_proj,         nullptr, 0, p_yx, 1024, 512, 1);
    sgemm_nt<<<dim3(4, 256), 256>>>(p_x, 512, W_x_proj + 512*512,    512, b_x_proj + 512,   nullptr, 0, p_ux, 512,  512, 1);

    // 3. kv projections
    sgemm_nt<<<dim3(8, 256), 256>>>(p_ur, 512, W_kv_rgb, 512, nullptr, nullptr, 0, p_kvr, 1024, 512, 0);
    sgemm_nt<<<dim3(8, 256), 256>>>(p_ux, 512, W_kv_x,   512, nullptr, nullptr, 0, p_kvx, 1024, 512, 0);

    // 4. attention: ctx_r (from kv_r), ctx_x (from kv_x); cross-applied
    attn_ktv<<<dim3(64, 16), 256>>>(p_kvr, p_attp);
    attn_ktv<<<dim3(64, 16), 256>>>(p_kvx, p_attp + (size_t)64 * 16 * 4096);
    attn_reduce_softmax<<<64, 64>>>(p_attp,                              p_ctx);               // ctx_r
    attn_reduce_softmax<<<64, 64>>>(p_attp + (size_t)64 * 16 * 4096,     p_ctx + 64 * 4096);   // ctx_x
    attn_qctx<<<dim3(64, 64), 256>>>(p_ur, p_ctx + 64 * 4096, p_yr + 512);  // o_rgb = q_rgb @ ctx_x
    attn_qctx<<<dim3(64, 64), 256>>>(p_ux, p_ctx,             p_yx + 512);  // o_x   = q_x   @ ctx_r

    // 5. out projections + residual, then LN (in-place on halves of fuse)
    sgemm_nt<<<dim3(4, 256), 256>>>(p_yr, 1024, W_out_rgb, 1024, b_out_rgb, p_r, 512, p_fuse,       1024, 1024, 0);
    sgemm_nt<<<dim3(4, 256), 256>>>(p_yx, 1024, W_out_x,   1024, b_out_x,   p_x, 512, p_fuse + 512, 1024, 1024, 0);
    layernorm_rows<<<32768, 128>>>(p_fuse,       1024, ln_rgb_g, ln_rgb_b);
    layernorm_rows<<<32768, 128>>>(p_fuse + 512, 1024, ln_x_g,   ln_x_b);

    // 6. residual + CE block
    sgemm_nt<<<dim3(4, 256), 256>>>(p_fuse, 1024, W_res, 1024, nullptr, nullptr, 0, p_res, 512, 1024, 0);
    sgemm_nt<<<dim3(4, 256), 256>>>(p_fuse, 1024, W_ce1, 1024, b_ce1,   nullptr, 0, p_t1,  512, 1024, 0);
    dwconv3x3<<<65536, 256>>>(p_t1, W_dw, b_dw, p_t2);
    sgemm_nt<<<dim3(4, 256), 256>>>(p_t2, 512, W_ce2, 512, b_ce2, nullptr, 0, p_t1, 512, 512, 0);

    // 7. bn1, add residual, bn2, final transposed write
    bn_stats_partial<<<256, 256>>>(p_t1, p_bnp);
    bn_stats_final<<<1, 512>>>(p_bnp, p_mu, p_rs);
    bn_apply_add<<<65536, 256>>>(p_t1, p_res, p_mu, p_rs, bn1_g, bn1_b, p_t2);
    bn_stats_partial<<<256, 256>>>(p_t2, p_bnp);
    bn_stats_final<<<1, 512>>>(p_bnp, p_mu, p_rs);
    bn_apply_transpose<<<tp_grid, tp_blk>>>(p_t2, p_mu, p_rs, bn2_g, bn2_b, out);
}

// round 4
// speedup vs baseline: 2.3398x; 2.3398x over previous
#include <cuda_runtime.h>
#include <cstdint>

// ---------------------------------------------------------------------------
// FeatureFusionModule: B=8, C=512, H=W=64, N=4096, heads=8, d=64
// GEMMs via warp-level mma.sync tf32 (sm_80-compatible path; tcgen05 is not
// available — harness compiles for plain sm_100).
// ---------------------------------------------------------------------------

#define Bb 8
#define Cc 512
#define Nn 4096

// ------------------------------- scratch -----------------------------------
__device__ float g_r   [(size_t)Bb * Nn * Cc];
__device__ float g_x   [(size_t)Bb * Nn * Cc];
__device__ float g_yr  [(size_t)Bb * Nn * 2 * Cc];
__device__ float g_yx  [(size_t)Bb * Nn * 2 * Cc];
__device__ float g_ur  [(size_t)Bb * Nn * Cc];
__device__ float g_ux  [(size_t)Bb * Nn * Cc];
__device__ float g_kvr [(size_t)Bb * Nn * 2 * Cc];
__device__ float g_kvx [(size_t)Bb * Nn * 2 * Cc];
__device__ float g_ctx [2 * 64 * 64 * 64];
__device__ float g_attp[2 * 64 * 16 * 64 * 64];
__device__ float g_fuse[(size_t)Bb * Nn * 2 * Cc];
__device__ float g_res [(size_t)Bb * Nn * Cc];
__device__ float g_t1  [(size_t)Bb * Nn * Cc];
__device__ float g_t2  [(size_t)Bb * Nn * Cc];
__device__ float g_bnp [2 * 256 * Cc];
__device__ float g_mu  [Cc];
__device__ float g_rs  [Cc];

// ----------------------------- helpers --------------------------------------
__device__ __forceinline__ uint32_t f2tf32(float f) {
    uint32_t r;
    asm("cvt.rna.tf32.f32 %0, %1;" : "=r"(r) : "f"(f));
    return r;
}

__device__ __forceinline__ void mma_tf32(float* d, const uint32_t* a, const uint32_t* b) {
    asm volatile(
        "mma.sync.aligned.m16n8k8.row.col.f32.tf32.tf32.f32 "
        "{%0,%1,%2,%3}, {%4,%5,%6,%7}, {%8,%9}, {%0,%1,%2,%3};"
        : "+f"(d[0]), "+f"(d[1]), "+f"(d[2]), "+f"(d[3])
        : "r"(a[0]), "r"(a[1]), "r"(a[2]), "r"(a[3]), "r"(b[0]), "r"(b[1]));
}

#define CP_ASYNC16(smem_u32, gptr) \
    asm volatile("cp.async.cg.shared.global [%0], [%1], 16;" :: "r"(smem_u32), "l"(gptr))
#define CP_COMMIT() asm volatile("cp.async.commit_group;" ::: "memory")
#define CP_WAIT0()  asm volatile("cp.async.wait_group 0;" ::: "memory")

// SMEM: As[2][128][20] | Bs[2][128][20]  (floats)  -> 80 KB dynamic
#define LDP 20
#define TILE_F (128 * LDP)
#define TC_SMEM (4 * TILE_F * 4)

// ------------------------------ tensor-core GEMM ----------------------------
// C[m,n] = act( sum_k A[m,k]*Bw[n,k] + bias[n] + resid[m,n] )
// block tile 128x128, 8 warps (2m x 4n), warp tile 64x32, k-chunk 16.
__global__ __launch_bounds__(256) void tc_gemm(
    const float* __restrict__ A, int lda,
    const float* __restrict__ Bw, int ldb,
    const float* __restrict__ bias,
    const float* __restrict__ resid, int ldr,
    float* __restrict__ C, int ldc,
    int K, int relu)
{
    extern __shared__ float sh[];
    float* As = sh;                 // [2][128][20]
    float* Bs = sh + 2 * TILE_F;    // [2][128][20]

    const int tid = threadIdx.x;
    const int wid = tid >> 5, lane = tid & 31;
    const int g = lane >> 2, t4 = lane & 3;
    const int wm = wid >> 2, wn = wid & 3;       // 2 x 4 warp grid
    const int bm = blockIdx.y * 128, bn = blockIdx.x * 128;
    const int mbase = wm * 64, nbase = wn * 32;

    const uint32_t sA = (uint32_t)__cvta_generic_to_shared(As);
    const uint32_t sB = (uint32_t)__cvta_generic_to_shared(Bs);

    float d[4][4][4];
    #pragma unroll
    for (int i = 0; i < 4; i++)
        #pragma unroll
        for (int j = 0; j < 4; j++)
            #pragma unroll
            for (int r = 0; r < 4; r++) d[i][j][r] = 0.f;

    const int row_s = tid >> 2;        // 0..63 (x2 halves)
    const int c4 = (tid & 3) * 4;      // 0,4,8,12

    auto stage = [&](int c, int buf) {
        const float* Ap = A + (size_t)bm * lda + c * 16;
        const float* Bp = Bw + (size_t)bn * ldb + c * 16;
        #pragma unroll
        for (int i = 0; i < 2; i++) {
            int row = row_s + i * 64;
            uint32_t da = sA + (buf * TILE_F + row * LDP + c4) * 4;
            uint32_t db = sB + (buf * TILE_F + row * LDP + c4) * 4;
            CP_ASYNC16(da, Ap + (size_t)row * lda + c4);
            CP_ASYNC16(db, Bp + (size_t)row * ldb + c4);
        }
        CP_COMMIT();
    };

    const int nc = K >> 4;
    stage(0, 0);
    int p = 0;
    for (int c = 0; c < nc; c++) {
        CP_WAIT0();
        __syncthreads();
        if (c + 1 < nc) stage(c + 1, p ^ 1);

        const float* Ab = As + p * TILE_F;
        const float* Bb2 = Bs + p * TILE_F;
        #pragma unroll
        for (int ks = 0; ks < 2; ks++) {
            const int k0 = ks * 8;
            uint32_t a[4][4], b[4][2];
            #pragma unroll
            for (int mt = 0; mt < 4; mt++) {
                const float* pa = Ab + (mbase + mt * 16 + g) * LDP + k0 + t4;
                a[mt][0] = f2tf32(pa[0]);
                a[mt][1] = f2tf32(pa[8 * LDP]);
                a[mt][2] = f2tf32(pa[4]);
                a[mt][3] = f2tf32(pa[8 * LDP + 4]);
            }
            #pragma unroll
            for (int nt = 0; nt < 4; nt++) {
                const float* pb = Bb2 + (nbase + nt * 8 + g) * LDP + k0 + t4;
                b[nt][0] = f2tf32(pb[0]);
                b[nt][1] = f2tf32(pb[4]);
            }
            #pragma unroll
            for (int mt = 0; mt < 4; mt++)
                #pragma unroll
                for (int nt = 0; nt < 4; nt++)
                    mma_tf32(d[mt][nt], a[mt], b[nt]);
        }
        p ^= 1;
    }

    // epilogue
    #pragma unroll
    for (int mt = 0; mt < 4; mt++) {
        #pragma unroll
        for (int half = 0; half < 2; half++) {
            const int m = bm + mbase + mt * 16 + g + half * 8;
            float* crow = C + (size_t)m * ldc;
            const float* rrow = resid ? resid + (size_t)m * ldr : nullptr;
            #pragma unroll
            for (int nt = 0; nt < 4; nt++) {
                const int n = bn + nbase + nt * 8 + t4 * 2;
                float vx = d[mt][nt][half * 2 + 0];
                float vy = d[mt][nt][half * 2 + 1];
                if (bias)  { vx += bias[n]; vy += bias[n + 1]; }
                if (rrow)  { vx += rrow[n]; vy += rrow[n + 1]; }
                if (relu)  { vx = fmaxf(vx, 0.f); vy = fmaxf(vy, 0.f); }
                *(float2*)(crow + n) = make_float2(vx, vy);
            }
        }
    }
}

// ------------------------- transpose NCHW -> (B,N,C) ------------------------
__global__ void transpose_cn_to_nc(const float* __restrict__ in, float* __restrict__ out) {
    __shared__ float tile[32][33];
    int b = blockIdx.z;
    int n0 = blockIdx.x * 32, c0 = blockIdx.y * 32;
    const float* ip = in + (size_t)b * Cc * Nn;
    float* op = out + (size_t)b * Nn * Cc;
    int tx = threadIdx.x, ty = threadIdx.y;
    #pragma unroll
    for (int i = ty; i < 32; i += 8)
        tile[i][tx] = ip[(size_t)(c0 + i) * Nn + n0 + tx];
    __syncthreads();
    #pragma unroll
    for (int i = ty; i < 32; i += 8)
        op[(size_t)(n0 + i) * Cc + c0 + tx] = tile[tx][i];
}

// --------------------------- attention: kT v partials -----------------------
__global__ __launch_bounds__(256) void attn_ktv(const float* __restrict__ kv,
                                                float* __restrict__ part) {
    __shared__ float ks[32][68];
    __shared__ float vs[32][68];
    int bh = blockIdx.x;
    int b = bh >> 3, h = bh & 7;
    int s = blockIdx.y;
    const float* kp = kv + (size_t)b * Nn * 1024 + h * 64;
    const float* vp = kp + 512;
    int tid = threadIdx.x;
    int td = tid >> 4, te = tid & 15;
    float acc[4][4];
    #pragma unroll
    for (int i = 0; i < 4; i++)
        #pragma unroll
        for (int j = 0; j < 4; j++) acc[i][j] = 0.f;

    for (int n0 = s * 256; n0 < s * 256 + 256; n0 += 32) {
        #pragma unroll
        for (int hh = 0; hh < 2; hh++) {
            int flat = tid + 256 * hh;
            int row = flat >> 4;
            int cv = (flat & 15) << 2;
            *(float4*)&ks[row][cv] = *(const float4*)(kp + (size_t)(n0 + row) * 1024 + cv);
            *(float4*)&vs[row][cv] = *(const float4*)(vp + (size_t)(n0 + row) * 1024 + cv);
        }
        __syncthreads();
        #pragma unroll
        for (int nn = 0; nn < 32; nn++) {
            float av[4], bv[4];
            float4 a4 = *(float4*)&ks[nn][td * 4];
            av[0]=a4.x; av[1]=a4.y; av[2]=a4.z; av[3]=a4.w;
            float4 b4 = *(float4*)&vs[nn][te * 4];
            bv[0]=b4.x; bv[1]=b4.y; bv[2]=b4.z; bv[3]=b4.w;
            #pragma unroll
            for (int i = 0; i < 4; i++)
                #pragma unroll
                for (int j = 0; j < 4; j++)
                    acc[i][j] += av[i] * bv[j];
        }
        __syncthreads();
    }
    float* pp = part + ((size_t)bh * 16 + s) * 4096;
    #pragma unroll
    for (int i = 0; i < 4; i++)
        #pragma unroll
        for (int j = 0; j < 4; j++)
            pp[(td * 4 + i) * 64 + te * 4 + j] = acc[i][j];
}

__global__ void attn_reduce_softmax(const float* __restrict__ part,
                                    float* __restrict__ ctx) {
    int bh = blockIdx.x;
    int e = threadIdx.x;
    float m[64];
    #pragma unroll
    for (int d = 0; d < 64; d++) {
        float ssum = 0.f;
        #pragma unroll
        for (int p = 0; p < 16; p++)
            ssum += part[((size_t)bh * 16 + p) * 4096 + d * 64 + e];
        m[d] = ssum * 0.125f;
    }
    float mx = -1e30f;
    #pragma unroll
    for (int d = 0; d < 64; d++) mx = fmaxf(mx, m[d]);
    float sum = 0.f;
    #pragma unroll
    for (int d = 0; d < 64; d++) { m[d] = expf(m[d] - mx); sum += m[d]; }
    float inv = 1.f / sum;
    #pragma unroll
    for (int d = 0; d < 64; d++)
        ctx[(size_t)bh * 4096 + d * 64 + e] = m[d] * inv;
}

__global__ __launch_bounds__(256) void attn_qctx(const float* __restrict__ q,
                                                 const float* __restrict__ ctx,
                                                 float* __restrict__ outp) {
    __shared__ float cs[64][68];
    __shared__ float qs[64][68];
    int bh = blockIdx.y;
    int b = bh >> 3, h = bh & 7;
    const float* cp = ctx + (size_t)bh * 4096;
    int tid = threadIdx.x;
    for (int i = tid; i < 4096; i += 256)
        cs[i >> 6][i & 63] = cp[i];
    int n0 = blockIdx.x * 64;
    const float* qp = q + (size_t)b * Nn * Cc + h * 64;
    #pragma unroll
    for (int j = 0; j < 4; j++) {
        int flat = tid + 256 * j;
        int row = flat >> 4;
        int cv = (flat & 15) << 2;
        *(float4*)&qs[row][cv] = *(const float4*)(qp + (size_t)(n0 + row) * Cc + cv);
    }
    __syncthreads();
    int tn = tid >> 3;
    int te = tid & 7;
    float acc0[8], acc1[8];
    #pragma unroll
    for (int j = 0; j < 8; j++) { acc0[j] = 0.f; acc1[j] = 0.f; }
    #pragma unroll 4
    for (int d = 0; d < 64; d++) {
        float qa = qs[tn][d];
        float qb = qs[tn + 32][d];
        float4 c0 = *(float4*)&cs[d][te * 8];
        float4 c1 = *(float4*)&cs[d][te * 8 + 4];
        float cv[8];
        cv[0]=c0.x; cv[1]=c0.y; cv[2]=c0.z; cv[3]=c0.w;
        cv[4]=c1.x; cv[5]=c1.y; cv[6]=c1.z; cv[7]=c1.w;
        #pragma unroll
        for (int j = 0; j < 8; j++) {
            acc0[j] += qa * cv[j];
            acc1[j] += qb * cv[j];
        }
    }
    float* o0 = outp + ((size_t)b * Nn + n0 + tn) * 1024 + h * 64 + te * 8;
    float* o1 = outp + ((size_t)b * Nn + n0 + tn + 32) * 1024 + h * 64 + te * 8;
    #pragma unroll
    for (int j = 0; j < 8; j++) { o0[j] = acc0[j]; o1[j] = acc1[j]; }
}

// ------------------------------ layernorm rows ------------------------------
__global__ __launch_bounds__(128) void layernorm_rows(float* __restrict__ base, int ld,
                                                      const float* __restrict__ gg,
                                                      const float* __restrict__ bb) {
    int row = blockIdx.x;
    float* p = base + (size_t)row * ld;
    int t = threadIdx.x;
    float v[4];
    float s = 0.f;
    #pragma unroll
    for (int i = 0; i < 4; i++) { v[i] = p[t + i * 128]; s += v[i]; }
    __shared__ float red[4];
    #pragma unroll
    for (int o = 16; o > 0; o >>= 1) s += __shfl_xor_sync(0xffffffffu, s, o);
    if ((t & 31) == 0) red[t >> 5] = s;
    __syncthreads();
    float mu = (red[0] + red[1] + red[2] + red[3]) * (1.f / 512.f);
    float q = 0.f;
    #pragma unroll
    for (int i = 0; i < 4; i++) { float d = v[i] - mu; q += d * d; }
    #pragma unroll
    for (int o = 16; o > 0; o >>= 1) q += __shfl_xor_sync(0xffffffffu, q, o);
    __syncthreads();
    if ((t & 31) == 0) red[t >> 5] = q;
    __syncthreads();
    float rs = rsqrtf((red[0] + red[1] + red[2] + red[3]) * (1.f / 512.f) + 1e-5f);
    #pragma unroll
    for (int i = 0; i < 4; i++) {
        int c = t + i * 128;
        p[c] = (v[i] - mu) * rs * gg[c] + bb[c];
    }
}

// --------------------------- depthwise 3x3 + relu ---------------------------
__global__ void dwconv3x3(const float* __restrict__ in, const float* __restrict__ w,
                          const float* __restrict__ bias, float* __restrict__ out) {
    int idx = blockIdx.x * 256 + threadIdx.x;
    int c = idx & 511;
    int n = (idx >> 9) & 4095;
    int b = idx >> 21;
    int h = n >> 6, ww = n & 63;
    float acc = bias[c];
    #pragma unroll
    for (int kh = 0; kh < 3; kh++) {
        int hh = h + kh - 1;
        if ((unsigned)hh >= 64u) continue;
        #pragma unroll
        for (int kw = 0; kw < 3; kw++) {
            int wc = ww + kw - 1;
            if ((unsigned)wc >= 64u) continue;
            acc += in[((size_t)b * Nn + hh * 64 + wc) * Cc + c] * w[c * 9 + kh * 3 + kw];
        }
    }
    out[idx] = fmaxf(acc, 0.f);
}

// ------------------------------- batchnorm ----------------------------------
__global__ __launch_bounds__(256) void bn_stats_partial(const float* __restrict__ X,
                                                        float* __restrict__ part) {
    int blk = blockIdx.x;
    const float* p = X + (size_t)blk * 128 * Cc;
    int c0 = threadIdx.x, c1 = threadIdx.x + 256;
    float s0 = 0.f, q0 = 0.f, s1 = 0.f, q1 = 0.f;
    for (int r = 0; r < 128; r++) {
        float a = p[(size_t)r * Cc + c0];
        s0 += a; q0 += a * a;
        float bv = p[(size_t)r * Cc + c1];
        s1 += bv; q1 += bv * bv;
    }
    part[(size_t)blk * Cc + c0] = s0;
    part[(size_t)blk * Cc + c1] = s1;
    part[(size_t)256 * Cc + blk * Cc + c0] = q0;
    part[(size_t)256 * Cc + blk * Cc + c1] = q1;
}

__global__ void bn_stats_final(const float* __restrict__ part,
                               float* __restrict__ mu, float* __restrict__ rs) {
    int c = threadIdx.x;
    float s = 0.f, q = 0.f;
    for (int p = 0; p < 256; p++) {
        s += part[(size_t)p * Cc + c];
        q += part[(size_t)256 * Cc + p * Cc + c];
    }
    float m = s * (1.f / 32768.f);
    float v = q * (1.f / 32768.f) - m * m;
    mu[c] = m;
    rs[c] = rsqrtf(v + 1e-5f);
}

__global__ void bn_apply_add(const float* __restrict__ t3, const float* __restrict__ res,
                             const float* __restrict__ mu, const float* __restrict__ rs,
                             const float* __restrict__ gg, const float* __restrict__ bb,
                             float* __restrict__ s) {
    int idx = blockIdx.x * 256 + threadIdx.x;
    int c = idx & 511;
    s[idx] = res[idx] + (t3[idx] - mu[c]) * rs[c] * gg[c] + bb[c];
}

__global__ void bn_apply_transpose(const float* __restrict__ s,
                                   const float* __restrict__ mu, const float* __restrict__ rs,
                                   const float* __restrict__ gg, const float* __restrict__ bb,
                                   float* __restrict__ out) {
    __shared__ float tile[32][33];
    int b = blockIdx.z;
    int n0 = blockIdx.x * 32, c0 = blockIdx.y * 32;
    const float* ps = s + (size_t)b * Nn * Cc;
    float* po = out + (size_t)b * Cc * Nn;
    int tx = threadIdx.x, ty = threadIdx.y;
    #pragma unroll
    for (int i = ty; i < 32; i += 8) {
        int c = c0 + tx;
        float v = ps[(size_t)(n0 + i) * Cc + c];
        tile[i][tx] = (v - mu[c]) * rs[c] * gg[c] + bb[c];
    }
    __syncthreads();
    #pragma unroll
    for (int i = ty; i < 32; i += 8)
        po[(size_t)(c0 + i) * Nn + n0 + tx] = tile[tx][i];
}

// --------------------------------- launch -----------------------------------
static void tc_gemm_go(const float* A, int lda, const float* Bw, int ldb,
                       const float* bias, const float* resid, int ldr,
                       float* C, int ldc, int M, int Ngemm, int K, int relu) {
    tc_gemm<<<dim3(Ngemm / 128, M / 128), 256, TC_SMEM>>>(
        A, lda, Bw, ldb, bias, resid, ldr, C, ldc, K, relu);
}

extern "C" void kernel_launch(void* const* d_in, const int* in_sizes, int n_in,
                              void* d_out, int out_size) {
    (void)in_sizes; (void)n_in; (void)out_size;
    const float* rgb        = (const float*)d_in[0];
    const float* x          = (const float*)d_in[1];
    const float* W_rgb_proj = (const float*)d_in[2];
    const float* b_rgb_proj = (const float*)d_in[3];
    const float* W_x_proj   = (const float*)d_in[4];
    const float* b_x_proj   = (const float*)d_in[5];
    const float* W_kv_rgb   = (const float*)d_in[6];
    const float* W_kv_x     = (const float*)d_in[7];
    const float* W_out_rgb  = (const float*)d_in[8];
    const float* b_out_rgb  = (const float*)d_in[9];
    const float* W_out_x    = (const float*)d_in[10];
    const float* b_out_x    = (const float*)d_in[11];
    const float* ln_rgb_g   = (const float*)d_in[12];
    const float* ln_rgb_b   = (const float*)d_in[13];
    const float* ln_x_g     = (const float*)d_in[14];
    const float* ln_x_b     = (const float*)d_in[15];
    const float* W_res      = (const float*)d_in[16];
    const float* W_ce1      = (const float*)d_in[17];
    const float* b_ce1      = (const float*)d_in[18];
    const float* W_dw       = (const float*)d_in[19];
    const float* b_dw       = (const float*)d_in[20];
    const float* W_ce2      = (const float*)d_in[21];
    const float* b_ce2      = (const float*)d_in[22];
    const float* bn1_g      = (const float*)d_in[23];
    const float* bn1_b      = (const float*)d_in[24];
    const float* bn2_g      = (const float*)d_in[25];
    const float* bn2_b      = (const float*)d_in[26];
    float* out = (float*)d_out;

    cudaFuncSetAttribute(tc_gemm, cudaFuncAttributeMaxDynamicSharedMemorySize, TC_SMEM);

    float *p_r, *p_x, *p_yr, *p_yx, *p_ur, *p_ux, *p_kvr, *p_kvx;
    float *p_ctx, *p_attp, *p_fuse, *p_res, *p_t1, *p_t2, *p_bnp, *p_mu, *p_rs;
    cudaGetSymbolAddress((void**)&p_r,    g_r);
    cudaGetSymbolAddress((void**)&p_x,    g_x);
    cudaGetSymbolAddress((void**)&p_yr,   g_yr);
    cudaGetSymbolAddress((void**)&p_yx,   g_yx);
    cudaGetSymbolAddress((void**)&p_ur,   g_ur);
    cudaGetSymbolAddress((void**)&p_ux,   g_ux);
    cudaGetSymbolAddress((void**)&p_kvr,  g_kvr);
    cudaGetSymbolAddress((void**)&p_kvx,  g_kvx);
    cudaGetSymbolAddress((void**)&p_ctx,  g_ctx);
    cudaGetSymbolAddress((void**)&p_attp, g_attp);
    cudaGetSymbolAddress((void**)&p_fuse, g_fuse);
    cudaGetSymbolAddress((void**)&p_res,  g_res);
    cudaGetSymbolAddress((void**)&p_t1,   g_t1);
    cudaGetSymbolAddress((void**)&p_t2,   g_t2);
    cudaGetSymbolAddress((void**)&p_bnp,  g_bnp);
    cudaGetSymbolAddress((void**)&p_mu,   g_mu);
    cudaGetSymbolAddress((void**)&p_rs,   g_rs);

    dim3 tp_grid(128, 16, 8), tp_blk(32, 8);

    // 1. transposes
    transpose_cn_to_nc<<<tp_grid, tp_blk>>>(rgb, p_r);
    transpose_cn_to_nc<<<tp_grid, tp_blk>>>(x,   p_x);

    // 2. projections (split y / u, relu)
    tc_gemm_go(p_r, 512, W_rgb_proj,           512, b_rgb_proj,       nullptr, 0, p_yr, 1024, 32768, 512, 512, 1);
    tc_gemm_go(p_r, 512, W_rgb_proj + 512*512, 512, b_rgb_proj + 512, nullptr, 0, p_ur, 512,  32768, 512, 512, 1);
    tc_gemm_go(p_x, 512, W_x_proj,             512, b_x_proj,         nullptr, 0, p_yx, 1024, 32768, 512, 512, 1);
    tc_gemm_go(p_x, 512, W_x_proj + 512*512,   512, b_x_proj + 512,   nullptr, 0, p_ux, 512,  32768, 512, 512, 1);

    // 3. kv projections
    tc_gemm_go(p_ur, 512, W_kv_rgb, 512, nullptr, nullptr, 0, p_kvr, 1024, 32768, 1024, 512, 0);
    tc_gemm_go(p_ux, 512, W_kv_x,   512, nullptr, nullptr, 0, p_kvx, 1024, 32768, 1024, 512, 0);

    // 4. attention (exact fp32)
    attn_ktv<<<dim3(64, 16), 256>>>(p_kvr, p_attp);
    attn_ktv<<<dim3(64, 16), 256>>>(p_kvx, p_attp + (size_t)64 * 16 * 4096);
    attn_reduce_softmax<<<64, 64>>>(p_attp,                          p_ctx);
    attn_reduce_softmax<<<64, 64>>>(p_attp + (size_t)64 * 16 * 4096, p_ctx + 64 * 4096);
    attn_qctx<<<dim3(64, 64), 256>>>(p_ur, p_ctx + 64 * 4096, p_yr + 512);  // o_rgb = q_rgb @ ctx_x
    attn_qctx<<<dim3(64, 64), 256>>>(p_ux, p_ctx,             p_yx + 512);  // o_x   = q_x   @ ctx_r

    // 5. out projections + residual, then LN
    tc_gemm_go(p_yr, 1024, W_out_rgb, 1024, b_out_rgb, p_r, 512, p_fuse,       1024, 32768, 512, 1024, 0);
    tc_gemm_go(p_yx, 1024, W_out_x,   1024, b_out_x,   p_x, 512, p_fuse + 512, 1024, 32768, 512, 1024, 0);
    layernorm_rows<<<32768, 128>>>(p_fuse,       1024, ln_rgb_g, ln_rgb_b);
    layernorm_rows<<<32768, 128>>>(p_fuse + 512, 1024, ln_x_g,   ln_x_b);

    // 6. residual + CE block
    tc_gemm_go(p_fuse, 1024, W_res, 1024, nullptr, nullptr, 0, p_res, 512, 32768, 512, 1024, 0);
    tc_gemm_go(p_fuse, 1024, W_ce1, 1024, b_ce1,   nullptr, 0, p_t1,  512, 32768, 512, 1024, 0);
    dwconv3x3<<<65536, 256>>>(p_t1, W_dw, b_dw, p_t2);
    tc_gemm_go(p_t2, 512, W_ce2, 512, b_ce2, nullptr, 0, p_t1, 512, 32768, 512, 512, 0);

    // 7. bn1, add residual, bn2, final transposed write
    bn_stats_partial<<<256, 256>>>(p_t1, p_bnp);
    bn_stats_final<<<1, 512>>>(p_bnp, p_mu, p_rs);
    bn_apply_add<<<65536, 256>>>(p_t1, p_res, p_mu, p_rs, bn1_g, bn1_b, p_t2);
    bn_stats_partial<<<256, 256>>>(p_t2, p_bnp);
    bn_stats_final<<<1, 512>>>(p_bnp, p_mu, p_rs);
    bn_apply_transpose<<<tp_grid, tp_blk>>>(p_t2, p_mu, p_rs, bn2_g, bn2_b, out);
}

// round 5
// speedup vs baseline: 2.3405x; 1.0003x over previous
#include <cuda_runtime.h>
#include <cstdint>

// ---------------------------------------------------------------------------
// FeatureFusionModule: B=8, C=512, H=W=64, N=4096, heads=8, d=64
// GEMMs via warp-level mma.sync tf32 (sm_80-compatible path; tcgen05 is not
// available — harness compiles for plain sm_100).
// ---------------------------------------------------------------------------

#define Bb 8
#define Cc 512
#define Nn 4096

// ------------------------------- scratch -----------------------------------
__device__ float g_r   [(size_t)Bb * Nn * Cc];
__device__ float g_x   [(size_t)Bb * Nn * Cc];
__device__ float g_yr  [(size_t)Bb * Nn * 2 * Cc];
__device__ float g_yx  [(size_t)Bb * Nn * 2 * Cc];
__device__ float g_ur  [(size_t)Bb * Nn * Cc];
__device__ float g_ux  [(size_t)Bb * Nn * Cc];
__device__ float g_kvr [(size_t)Bb * Nn * 2 * Cc];
__device__ float g_kvx [(size_t)Bb * Nn * 2 * Cc];
__device__ float g_ctx [2 * 64 * 64 * 64];
__device__ float g_attp[2 * 64 * 16 * 64 * 64];
__device__ float g_fuse[(size_t)Bb * Nn * 2 * Cc];
__device__ float g_res [(size_t)Bb * Nn * Cc];
__device__ float g_t1  [(size_t)Bb * Nn * Cc];
__device__ float g_t2  [(size_t)Bb * Nn * Cc];
__device__ float g_bnp [2 * 256 * Cc];
__device__ float g_mu  [Cc];
__device__ float g_rs  [Cc];

// ----------------------------- helpers --------------------------------------
__device__ __forceinline__ uint32_t f2tf32(float f) {
    uint32_t r;
    asm("cvt.rna.tf32.f32 %0, %1;" : "=r"(r) : "f"(f));
    return r;
}

__device__ __forceinline__ void mma_tf32(float* d, const uint32_t* a, const uint32_t* b) {
    asm volatile(
        "mma.sync.aligned.m16n8k8.row.col.f32.tf32.tf32.f32 "
        "{%0,%1,%2,%3}, {%4,%5,%6,%7}, {%8,%9}, {%0,%1,%2,%3};"
        : "+f"(d[0]), "+f"(d[1]), "+f"(d[2]), "+f"(d[3])
        : "r"(a[0]), "r"(a[1]), "r"(a[2]), "r"(a[3]), "r"(b[0]), "r"(b[1]));
}

#define CP_ASYNC16(smem_u32, gptr) \
    asm volatile("cp.async.cg.shared.global [%0], [%1], 16;" :: "r"(smem_u32), "l"(gptr))
#define CP_COMMIT() asm volatile("cp.async.commit_group;" ::: "memory")
#define CP_WAIT0()  asm volatile("cp.async.wait_group 0;" ::: "memory")

// SMEM: As[2][128][20] | Bs[2][128][20]  (floats)  -> 80 KB dynamic
#define LDP 20
#define TILE_F (128 * LDP)
#define TC_SMEM (4 * TILE_F * 4)

// ------------------------------ tensor-core GEMM ----------------------------
// C[m,n] = act( sum_k A[m,k]*Bw[n,k] + bias[n] + resid[m,n] )
// block tile 128x128, 8 warps (2m x 4n), warp tile 64x32, k-chunk 16.
__global__ __launch_bounds__(256) void tc_gemm(
    const float* __restrict__ A, int lda,
    const float* __restrict__ Bw, int ldb,
    const float* __restrict__ bias,
    const float* __restrict__ resid, int ldr,
    float* __restrict__ C, int ldc,
    int K, int relu)
{
    extern __shared__ float sh[];
    float* As = sh;                 // [2][128][20]
    float* Bs = sh + 2 * TILE_F;    // [2][128][20]

    const int tid = threadIdx.x;
    const int wid = tid >> 5, lane = tid & 31;
    const int g = lane >> 2, t4 = lane & 3;
    const int wm = wid >> 2, wn = wid & 3;       // 2 x 4 warp grid
    const int bm = blockIdx.y * 128, bn = blockIdx.x * 128;
    const int mbase = wm * 64, nbase = wn * 32;

    const uint32_t sA = (uint32_t)__cvta_generic_to_shared(As);
    const uint32_t sB = (uint32_t)__cvta_generic_to_shared(Bs);

    float d[4][4][4];
    #pragma unroll
    for (int i = 0; i < 4; i++)
        #pragma unroll
        for (int j = 0; j < 4; j++)
            #pragma unroll
            for (int r = 0; r < 4; r++) d[i][j][r] = 0.f;

    const int row_s = tid >> 2;        // 0..63 (x2 halves)
    const int c4 = (tid & 3) * 4;      // 0,4,8,12

    auto stage = [&](int c, int buf) {
        const float* Ap = A + (size_t)bm * lda + c * 16;
        const float* Bp = Bw + (size_t)bn * ldb + c * 16;
        #pragma unroll
        for (int i = 0; i < 2; i++) {
            int row = row_s + i * 64;
            uint32_t da = sA + (buf * TILE_F + row * LDP + c4) * 4;
            uint32_t db = sB + (buf * TILE_F + row * LDP + c4) * 4;
            CP_ASYNC16(da, Ap + (size_t)row * lda + c4);
            CP_ASYNC16(db, Bp + (size_t)row * ldb + c4);
        }
        CP_COMMIT();
    };

    const int nc = K >> 4;
    stage(0, 0);
    int p = 0;
    for (int c = 0; c < nc; c++) {
        CP_WAIT0();
        __syncthreads();
        if (c + 1 < nc) stage(c + 1, p ^ 1);

        const float* Ab = As + p * TILE_F;
        const float* Bb2 = Bs + p * TILE_F;
        #pragma unroll
        for (int ks = 0; ks < 2; ks++) {
            const int k0 = ks * 8;
            uint32_t a[4][4], b[4][2];
            #pragma unroll
            for (int mt = 0; mt < 4; mt++) {
                const float* pa = Ab + (mbase + mt * 16 + g) * LDP + k0 + t4;
                a[mt][0] = f2tf32(pa[0]);
                a[mt][1] = f2tf32(pa[8 * LDP]);
                a[mt][2] = f2tf32(pa[4]);
                a[mt][3] = f2tf32(pa[8 * LDP + 4]);
            }
            #pragma unroll
            for (int nt = 0; nt < 4; nt++) {
                const float* pb = Bb2 + (nbase + nt * 8 + g) * LDP + k0 + t4;
                b[nt][0] = f2tf32(pb[0]);
                b[nt][1] = f2tf32(pb[4]);
            }
            #pragma unroll
            for (int mt = 0; mt < 4; mt++)
                #pragma unroll
                for (int nt = 0; nt < 4; nt++)
                    mma_tf32(d[mt][nt], a[mt], b[nt]);
        }
        p ^= 1;
    }

    // epilogue
    #pragma unroll
    for (int mt = 0; mt < 4; mt++) {
        #pragma unroll
        for (int half = 0; half < 2; half++) {
            const int m = bm + mbase + mt * 16 + g + half * 8;
            float* crow = C + (size_t)m * ldc;
            const float* rrow = resid ? resid + (size_t)m * ldr : nullptr;
            #pragma unroll
            for (int nt = 0; nt < 4; nt++) {
                const int n = bn + nbase + nt * 8 + t4 * 2;
                float vx = d[mt][nt][half * 2 + 0];
                float vy = d[mt][nt][half * 2 + 1];
                if (bias)  { vx += bias[n]; vy += bias[n + 1]; }
                if (rrow)  { vx += rrow[n]; vy += rrow[n + 1]; }
                if (relu)  { vx = fmaxf(vx, 0.f); vy = fmaxf(vy, 0.f); }
                *(float2*)(crow + n) = make_float2(vx, vy);
            }
        }
    }
}

// ------------------------- transpose NCHW -> (B,N,C) ------------------------
__global__ void transpose_cn_to_nc(const float* __restrict__ in, float* __restrict__ out) {
    __shared__ float tile[32][33];
    int b = blockIdx.z;
    int n0 = blockIdx.x * 32, c0 = blockIdx.y * 32;
    const float* ip = in + (size_t)b * Cc * Nn;
    float* op = out + (size_t)b * Nn * Cc;
    int tx = threadIdx.x, ty = threadIdx.y;
    #pragma unroll
    for (int i = ty; i < 32; i += 8)
        tile[i][tx] = ip[(size_t)(c0 + i) * Nn + n0 + tx];
    __syncthreads();
    #pragma unroll
    for (int i = ty; i < 32; i += 8)
        op[(size_t)(n0 + i) * Cc + c0 + tx] = tile[tx][i];
}

// --------------------------- attention: kT v partials -----------------------
__global__ __launch_bounds__(256) void attn_ktv(const float* __restrict__ kv,
                                                float* __restrict__ part) {
    __shared__ float ks[32][68];
    __shared__ float vs[32][68];
    int bh = blockIdx.x;
    int b = bh >> 3, h = bh & 7;
    int s = blockIdx.y;
    const float* kp = kv + (size_t)b * Nn * 1024 + h * 64;
    const float* vp = kp + 512;
    int tid = threadIdx.x;
    int td = tid >> 4, te = tid & 15;
    float acc[4][4];
    #pragma unroll
    for (int i = 0; i < 4; i++)
        #pragma unroll
        for (int j = 0; j < 4; j++) acc[i][j] = 0.f;

    for (int n0 = s * 256; n0 < s * 256 + 256; n0 += 32) {
        #pragma unroll
        for (int hh = 0; hh < 2; hh++) {
            int flat = tid + 256 * hh;
            int row = flat >> 4;
            int cv = (flat & 15) << 2;
            *(float4*)&ks[row][cv] = *(const float4*)(kp + (size_t)(n0 + row) * 1024 + cv);
            *(float4*)&vs[row][cv] = *(const float4*)(vp + (size_t)(n0 + row) * 1024 + cv);
        }
        __syncthreads();
        #pragma unroll
        for (int nn = 0; nn < 32; nn++) {
            float av[4], bv[4];
            float4 a4 = *(float4*)&ks[nn][td * 4];
            av[0]=a4.x; av[1]=a4.y; av[2]=a4.z; av[3]=a4.w;
            float4 b4 = *(float4*)&vs[nn][te * 4];
            bv[0]=b4.x; bv[1]=b4.y; bv[2]=b4.z; bv[3]=b4.w;
            #pragma unroll
            for (int i = 0; i < 4; i++)
                #pragma unroll
                for (int j = 0; j < 4; j++)
                    acc[i][j] += av[i] * bv[j];
        }
        __syncthreads();
    }
    float* pp = part + ((size_t)bh * 16 + s) * 4096;
    #pragma unroll
    for (int i = 0; i < 4; i++)
        #pragma unroll
        for (int j = 0; j < 4; j++)
            pp[(td * 4 + i) * 64 + te * 4 + j] = acc[i][j];
}

__global__ void attn_reduce_softmax(const float* __restrict__ part,
                                    float* __restrict__ ctx) {
    int bh = blockIdx.x;
    int e = threadIdx.x;
    float m[64];
    #pragma unroll
    for (int d = 0; d < 64; d++) {
        float ssum = 0.f;
        #pragma unroll
        for (int p = 0; p < 16; p++)
            ssum += part[((size_t)bh * 16 + p) * 4096 + d * 64 + e];
        m[d] = ssum * 0.125f;
    }
    float mx = -1e30f;
    #pragma unroll
    for (int d = 0; d < 64; d++) mx = fmaxf(mx, m[d]);
    float sum = 0.f;
    #pragma unroll
    for (int d = 0; d < 64; d++) { m[d] = expf(m[d] - mx); sum += m[d]; }
    float inv = 1.f / sum;
    #pragma unroll
    for (int d = 0; d < 64; d++)
        ctx[(size_t)bh * 4096 + d * 64 + e] = m[d] * inv;
}

__global__ __launch_bounds__(256) void attn_qctx(const float* __restrict__ q,
                                                 const float* __restrict__ ctx,
                                                 float* __restrict__ outp) {
    __shared__ float cs[64][68];
    __shared__ float qs[64][68];
    int bh = blockIdx.y;
    int b = bh >> 3, h = bh & 7;
    const float* cp = ctx + (size_t)bh * 4096;
    int tid = threadIdx.x;
    for (int i = tid; i < 4096; i += 256)
        cs[i >> 6][i & 63] = cp[i];
    int n0 = blockIdx.x * 64;
    const float* qp = q + (size_t)b * Nn * Cc + h * 64;
    #pragma unroll
    for (int j = 0; j < 4; j++) {
        int flat = tid + 256 * j;
        int row = flat >> 4;
        int cv = (flat & 15) << 2;
        *(float4*)&qs[row][cv] = *(const float4*)(qp + (size_t)(n0 + row) * Cc + cv);
    }
    __syncthreads();
    int tn = tid >> 3;
    int te = tid & 7;
    float acc0[8], acc1[8];
    #pragma unroll
    for (int j = 0; j < 8; j++) { acc0[j] = 0.f; acc1[j] = 0.f; }
    #pragma unroll 4
    for (int d = 0; d < 64; d++) {
        float qa = qs[tn][d];
        float qb = qs[tn + 32][d];
        float4 c0 = *(float4*)&cs[d][te * 8];
        float4 c1 = *(float4*)&cs[d][te * 8 + 4];
        float cv[8];
        cv[0]=c0.x; cv[1]=c0.y; cv[2]=c0.z; cv[3]=c0.w;
        cv[4]=c1.x; cv[5]=c1.y; cv[6]=c1.z; cv[7]=c1.w;
        #pragma unroll
        for (int j = 0; j < 8; j++) {
            acc0[j] += qa * cv[j];
            acc1[j] += qb * cv[j];
        }
    }
    float* o0 = outp + ((size_t)b * Nn + n0 + tn) * 1024 + h * 64 + te * 8;
    float* o1 = outp + ((size_t)b * Nn + n0 + tn + 32) * 1024 + h * 64 + te * 8;
    #pragma unroll
    for (int j = 0; j < 8; j++) { o0[j] = acc0[j]; o1[j] = acc1[j]; }
}

// ------------------------------ layernorm rows ------------------------------
__global__ __launch_bounds__(128) void layernorm_rows(float* __restrict__ base, int ld,
                                                      const float* __restrict__ gg,
                                                      const float* __restrict__ bb) {
    int row = blockIdx.x;
    float* p = base + (size_t)row * ld;
    int t = threadIdx.x;
    float v[4];
    float s = 0.f;
    #pragma unroll
    for (int i = 0; i < 4; i++) { v[i] = p[t + i * 128]; s += v[i]; }
    __shared__ float red[4];
    #pragma unroll
    for (int o = 16; o > 0; o >>= 1) s += __shfl_xor_sync(0xffffffffu, s, o);
    if ((t & 31) == 0) red[t >> 5] = s;
    __syncthreads();
    float mu = (red[0] + red[1] + red[2] + red[3]) * (1.f / 512.f);
    float q = 0.f;
    #pragma unroll
    for (int i = 0; i < 4; i++) { float d = v[i] - mu; q += d * d; }
    #pragma unroll
    for (int o = 16; o > 0; o >>= 1) q += __shfl_xor_sync(0xffffffffu, q, o);
    __syncthreads();
    if ((t & 31) == 0) red[t >> 5] = q;
    __syncthreads();
    float rs = rsqrtf((red[0] + red[1] + red[2] + red[3]) * (1.f / 512.f) + 1e-5f);
    #pragma unroll
    for (int i = 0; i < 4; i++) {
        int c = t + i * 128;
        p[c] = (v[i] - mu) * rs * gg[c] + bb[c];
    }
}

// --------------------------- depthwise 3x3 + relu ---------------------------
__global__ void dwconv3x3(const float* __restrict__ in, const float* __restrict__ w,
                          const float* __restrict__ bias, float* __restrict__ out) {
    int idx = blockIdx.x * 256 + threadIdx.x;
    int c = idx & 511;
    int n = (idx >> 9) & 4095;
    int b = idx >> 21;
    int h = n >> 6, ww = n & 63;
    float acc = bias[c];
    #pragma unroll
    for (int kh = 0; kh < 3; kh++) {
        int hh = h + kh - 1;
        if ((unsigned)hh >= 64u) continue;
        #pragma unroll
        for (int kw = 0; kw < 3; kw++) {
            int wc = ww + kw - 1;
            if ((unsigned)wc >= 64u) continue;
            acc += in[((size_t)b * Nn + hh * 64 + wc) * Cc + c] * w[c * 9 + kh * 3 + kw];
        }
    }
    out[idx] = fmaxf(acc, 0.f);
}

// ------------------------------- batchnorm ----------------------------------
__global__ __launch_bounds__(256) void bn_stats_partial(const float* __restrict__ X,
                                                        float* __restrict__ part) {
    int blk = blockIdx.x;
    const float* p = X + (size_t)blk * 128 * Cc;
    int c0 = threadIdx.x, c1 = threadIdx.x + 256;
    float s0 = 0.f, q0 = 0.f, s1 = 0.f, q1 = 0.f;
    for (int r = 0; r < 128; r++) {
        float a = p[(size_t)r * Cc + c0];
        s0 += a; q0 += a * a;
        float bv = p[(size_t)r * Cc + c1];
        s1 += bv; q1 += bv * bv;
    }
    part[(size_t)blk * Cc + c0] = s0;
    part[(size_t)blk * Cc + c1] = s1;
    part[(size_t)256 * Cc + blk * Cc + c0] = q0;
    part[(size_t)256 * Cc + blk * Cc + c1] = q1;
}

__global__ void bn_stats_final(const float* __restrict__ part,
                               float* __restrict__ mu, float* __restrict__ rs) {
    int c = threadIdx.x;
    float s = 0.f, q = 0.f;
    for (int p = 0; p < 256; p++) {
        s += part[(size_t)p * Cc + c];
        q += part[(size_t)256 * Cc + p * Cc + c];
    }
    float m = s * (1.f / 32768.f);
    float v = q * (1.f / 32768.f) - m * m;
    mu[c] = m;
    rs[c] = rsqrtf(v + 1e-5f);
}

__global__ void bn_apply_add(const float* __restrict__ t3, const float* __restrict__ res,
                             const float* __restrict__ mu, const float* __restrict__ rs,
                             const float* __restrict__ gg, const float* __restrict__ bb,
                             float* __restrict__ s) {
    int idx = blockIdx.x * 256 + threadIdx.x;
    int c = idx & 511;
    s[idx] = res[idx] + (t3[idx] - mu[c]) * rs[c] * gg[c] + bb[c];
}

__global__ void bn_apply_transpose(const float* __restrict__ s,
                                   const float* __restrict__ mu, const float* __restrict__ rs,
                                   const float* __restrict__ gg, const float* __restrict__ bb,
                                   float* __restrict__ out) {
    __shared__ float tile[32][33];
    int b = blockIdx.z;
    int n0 = blockIdx.x * 32, c0 = blockIdx.y * 32;
    const float* ps = s + (size_t)b * Nn * Cc;
    float* po = out + (size_t)b * Cc * Nn;
    int tx = threadIdx.x, ty = threadIdx.y;
    #pragma unroll
    for (int i = ty; i < 32; i += 8) {
        int c = c0 + tx;
        float v = ps[(size_t)(n0 + i) * Cc + c];
        tile[i][tx] = (v - mu[c]) * rs[c] * gg[c] + bb[c];
    }
    __syncthreads();
    #pragma unroll
    for (int i = ty; i < 32; i += 8)
        po[(size_t)(c0 + i) * Nn + n0 + tx] = tile[tx][i];
}

// --------------------------------- launch -----------------------------------
static void tc_gemm_go(const float* A, int lda, const float* Bw, int ldb,
                       const float* bias, const float* resid, int ldr,
                       float* C, int ldc, int M, int Ngemm, int K, int relu) {
    tc_gemm<<<dim3(Ngemm / 128, M / 128), 256, TC_SMEM>>>(
        A, lda, Bw, ldb, bias, resid, ldr, C, ldc, K, relu);
}

extern "C" void kernel_launch(void* const* d_in, const int* in_sizes, int n_in,
                              void* d_out, int out_size) {
    (void)in_sizes; (void)n_in; (void)out_size;
    const float* rgb        = (const float*)d_in[0];
    const float* x          = (const float*)d_in[1];
    const float* W_rgb_proj = (const float*)d_in[2];
    const float* b_rgb_proj = (const float*)d_in[3];
    const float* W_x_proj   = (const float*)d_in[4];
    const float* b_x_proj   = (const float*)d_in[5];
    const float* W_kv_rgb   = (const float*)d_in[6];
    const float* W_kv_x     = (const float*)d_in[7];
    const float* W_out_rgb  = (const float*)d_in[8];
    const float* b_out_rgb  = (const float*)d_in[9];
    const float* W_out_x    = (const float*)d_in[10];
    const float* b_out_x    = (const float*)d_in[11];
    const float* ln_rgb_g   = (const float*)d_in[12];
    const float* ln_rgb_b   = (const float*)d_in[13];
    const float* ln_x_g     = (const float*)d_in[14];
    const float* ln_x_b     = (const float*)d_in[15];
    const float* W_res      = (const float*)d_in[16];
    const float* W_ce1      = (const float*)d_in[17];
    const float* b_ce1      = (const float*)d_in[18];
    const float* W_dw       = (const float*)d_in[19];
    const float* b_dw       = (const float*)d_in[20];
    const float* W_ce2      = (const float*)d_in[21];
    const float* b_ce2      = (const float*)d_in[22];
    const float* bn1_g      = (const float*)d_in[23];
    const float* bn1_b      = (const float*)d_in[24];
    const float* bn2_g      = (const float*)d_in[25];
    const float* bn2_b      = (const float*)d_in[26];
    float* out = (float*)d_out;

    cudaFuncSetAttribute(tc_gemm, cudaFuncAttributeMaxDynamicSharedMemorySize, TC_SMEM);

    float *p_r, *p_x, *p_yr, *p_yx, *p_ur, *p_ux, *p_kvr, *p_kvx;
    float *p_ctx, *p_attp, *p_fuse, *p_res, *p_t1, *p_t2, *p_bnp, *p_mu, *p_rs;
    cudaGetSymbolAddress((void**)&p_r,    g_r);
    cudaGetSymbolAddress((void**)&p_x,    g_x);
    cudaGetSymbolAddress((void**)&p_yr,   g_yr);
    cudaGetSymbolAddress((void**)&p_yx,   g_yx);
    cudaGetSymbolAddress((void**)&p_ur,   g_ur);
    cudaGetSymbolAddress((void**)&p_ux,   g_ux);
    cudaGetSymbolAddress((void**)&p_kvr,  g_kvr);
    cudaGetSymbolAddress((void**)&p_kvx,  g_kvx);
    cudaGetSymbolAddress((void**)&p_ctx,  g_ctx);
    cudaGetSymbolAddress((void**)&p_attp, g_attp);
    cudaGetSymbolAddress((void**)&p_fuse, g_fuse);
    cudaGetSymbolAddress((void**)&p_res,  g_res);
    cudaGetSymbolAddress((void**)&p_t1,   g_t1);
    cudaGetSymbolAddress((void**)&p_t2,   g_t2);
    cudaGetSymbolAddress((void**)&p_bnp,  g_bnp);
    cudaGetSymbolAddress((void**)&p_mu,   g_mu);
    cudaGetSymbolAddress((void**)&p_rs,   g_rs);

    dim3 tp_grid(128, 16, 8), tp_blk(32, 8);

    // 1. transposes
    transpose_cn_to_nc<<<tp_grid, tp_blk>>>(rgb, p_r);
    transpose_cn_to_nc<<<tp_grid, tp_blk>>>(x,   p_x);

    // 2. projections (split y / u, relu)
    tc_gemm_go(p_r, 512, W_rgb_proj,           512, b_rgb_proj,       nullptr, 0, p_yr, 1024, 32768, 512, 512, 1);
    tc_gemm_go(p_r, 512, W_rgb_proj + 512*512, 512, b_rgb_proj + 512, nullptr, 0, p_ur, 512,  32768, 512, 512, 1);
    tc_gemm_go(p_x, 512, W_x_proj,             512, b_x_proj,         nullptr, 0, p_yx, 1024, 32768, 512, 512, 1);
    tc_gemm_go(p_x, 512, W_x_proj + 512*512,   512, b_x_proj + 512,   nullptr, 0, p_ux, 512,  32768, 512, 512, 1);

    // 3. kv projections
    tc_gemm_go(p_ur, 512, W_kv_rgb, 512, nullptr, nullptr, 0, p_kvr, 1024, 32768, 1024, 512, 0);
    tc_gemm_go(p_ux, 512, W_kv_x,   512, nullptr, nullptr, 0, p_kvx, 1024, 32768, 1024, 512, 0);

    // 4. attention (exact fp32)
    attn_ktv<<<dim3(64, 16), 256>>>(p_kvr, p_attp);
    attn_ktv<<<dim3(64, 16), 256>>>(p_kvx, p_attp + (size_t)64 * 16 * 4096);
    attn_reduce_softmax<<<64, 64>>>(p_attp,                          p_ctx);
    attn_reduce_softmax<<<64, 64>>>(p_attp + (size_t)64 * 16 * 4096, p_ctx + 64 * 4096);
    attn_qctx<<<dim3(64, 64), 256>>>(p_ur, p_ctx + 64 * 4096, p_yr + 512);  // o_rgb = q_rgb @ ctx_x
    attn_qctx<<<dim3(64, 64), 256>>>(p_ux, p_ctx,             p_yx + 512);  // o_x   = q_x   @ ctx_r

    // 5. out projections + residual, then LN
    tc_gemm_go(p_yr, 1024, W_out_rgb, 1024, b_out_rgb, p_r, 512, p_fuse,       1024, 32768, 512, 1024, 0);
    tc_gemm_go(p_yx, 1024, W_out_x,   1024, b_out_x,   p_x, 512, p_fuse + 512, 1024, 32768, 512, 1024, 0);
    layernorm_rows<<<32768, 128>>>(p_fuse,       1024, ln_rgb_g, ln_rgb_b);
    layernorm_rows<<<32768, 128>>>(p_fuse + 512, 1024, ln_x_g,   ln_x_b);

    // 6. residual + CE block
    tc_gemm_go(p_fuse, 1024, W_res, 1024, nullptr, nullptr, 0, p_res, 512, 32768, 512, 1024, 0);
    tc_gemm_go(p_fuse, 1024, W_ce1, 1024, b_ce1,   nullptr, 0, p_t1,  512, 32768, 512, 1024, 0);
    dwconv3x3<<<65536, 256>>>(p_t1, W_dw, b_dw, p_t2);
    tc_gemm_go(p_t2, 512, W_ce2, 512, b_ce2, nullptr, 0, p_t1, 512, 32768, 512, 512, 0);

    // 7. bn1, add residual, bn2, final transposed write
    bn_stats_partial<<<256, 256>>>(p_t1, p_bnp);
    bn_stats_final<<<1, 512>>>(p_bnp, p_mu, p_rs);
    bn_apply_add<<<65536, 256>>>(p_t1, p_res, p_mu, p_rs, bn1_g, bn1_b, p_t2);
    bn_stats_partial<<<256, 256>>>(p_t2, p_bnp);
    bn_stats_final<<<1, 512>>>(p_bnp, p_mu, p_rs);
    bn_apply_transpose<<<tp_grid, tp_blk>>>(p_t2, p_mu, p_rs, bn2_g, bn2_b, out);
}